// round 9
// baseline (speedup 1.0000x reference)
#include <cuda_runtime.h>
#include <cuda_bf16.h>

// Entmax15: out = clip(X - tau*, 0)^2 with sum(out) = 1 per row,
// X = (masked_scores - rowmax) * 0.5.
//
// tau* via Newton on g(tau) = sqrt(f(tau)) - 1, f(tau) = sum max(X-tau,0)^2
// (g convex left of the root: each piece of f is K(t-c)^2+v, so
// 2 f f'' - f'^2 = 4Kv >= 0; Newton from tau=-1 is monotone, no overshoot):
//   dlt = (S2 - sqrt(S2)) / S1.
//
// R9: 2 rows per CTA. Row1's 8 LDG.128 are issued before row0's solve, so
// row0's ~1100-cycle memory-silent solve overlaps row1's loads (R8 showed
// DRAM idle ~= solve fraction ~= 15%). Shape stays 128 thr x 16 elem/row
// (R7: per-thread front-batched LDG depth, not occupancy, drives HBM BW).
// One barrier per solve iteration; every thread combines the 4 warp partials
// (tau bitwise-uniform -> uniform loop exit, no broadcast needed); double-
// buffered warp-partial slots make it race-free; per-row smem buffers keep
// solve0's epilogue reads safe from solve1's first writes.
// redux.sync.f32 unavailable on sm_103a (R5) -> shuffle-tree warp reduce.

constexpr int S_LEN   = 2048;
constexpr int THREADS = 128;
constexpr int WARPS   = THREADS / 32;
constexpr int EPT     = S_LEN / THREADS;      // 16 elems per thread per row
constexpr int V4      = EPT / 4;              // 4 float4 per thread per row
constexpr int ROW4    = S_LEN / 4;            // float4 stride between rows
constexpr int ROWS_PER_CTA = 2;
constexpr float NEG_FILL = -1e4f;

struct Smem {
    float  shmax[ROWS_PER_CTA][WARPS];
    float2 red[ROWS_PER_CTA][2][WARPS];   // per-row, double-buffered (S1,S2)
};

// Solve for tau on the (already transformed) per-thread slice x[EPT].
// Uniform across the block on exit.
__device__ __forceinline__ float solve_tau(const float x[EPT],
                                           float2 (*red)[WARPS],
                                           int warp, int lane)
{
    float tau = -1.0f;   // max element alone contributes 1 => f(-1) >= 1
    int   p   = 0;
    #pragma unroll 1
    for (int it = 0; it < 20; ++it) {
        float s1a = 0.0f, s1b = 0.0f, s2a = 0.0f, s2b = 0.0f;
        #pragma unroll
        for (int i = 0; i < EPT; i += 2) {
            float d0 = fmaxf(x[i]     - tau, 0.0f);
            float d1 = fmaxf(x[i + 1] - tau, 0.0f);
            s1a += d0;                s1b += d1;
            s2a  = fmaf(d0, d0, s2a); s2b  = fmaf(d1, d1, s2b);
        }
        float s1 = s1a + s1b;
        float s2 = s2a + s2b;
        #pragma unroll
        for (int o = 16; o; o >>= 1) {
            s1 += __shfl_xor_sync(0xffffffffu, s1, o);
            s2 += __shfl_xor_sync(0xffffffffu, s2, o);
        }
        if (lane == 0) red[p][warp] = make_float2(s1, s2);
        __syncthreads();

        float2 r0 = red[p][0], r1 = red[p][1], r2 = red[p][2], r3 = red[p][3];
        float S1 = (r0.x + r1.x) + (r2.x + r3.x);
        float S2 = (r0.y + r1.y) + (r2.y + r3.y);
        p ^= 1;

        float dlt = __fdividef(S2 - sqrtf(S2), fmaxf(S1, 1e-20f));
        tau += dlt;
        if (dlt < 1e-6f) break;     // uniform: identical ops on identical data
    }
    return tau;
}

__device__ __forceinline__ float block_max_transform(float x[EPT],
                                                     float* shmax,
                                                     int warp, int lane)
{
    float mx = x[0];
    #pragma unroll
    for (int i = 1; i < EPT; ++i) mx = fmaxf(mx, x[i]);
    #pragma unroll
    for (int o = 16; o; o >>= 1) mx = fmaxf(mx, __shfl_xor_sync(0xffffffffu, mx, o));
    if (lane == 0) shmax[warp] = mx;
    __syncthreads();
    mx = fmaxf(fmaxf(shmax[0], shmax[1]), fmaxf(shmax[2], shmax[3]));
    const float mxh = mx * 0.5f;
    #pragma unroll
    for (int i = 0; i < EPT; ++i) x[i] = fmaf(x[i], 0.5f, -mxh);
    return mx;
}

__device__ __forceinline__ void emit(float4* o4, const float x[EPT], float tau, int tid)
{
    #pragma unroll
    for (int v = 0; v < V4; ++v) {
        float4 r;
        float d;
        d = fmaxf(x[v * 4 + 0] - tau, 0.0f); r.x = d * d;
        d = fmaxf(x[v * 4 + 1] - tau, 0.0f); r.y = d * d;
        d = fmaxf(x[v * 4 + 2] - tau, 0.0f); r.z = d * d;
        d = fmaxf(x[v * 4 + 3] - tau, 0.0f); r.w = d * d;
        o4[tid + v * THREADS] = r;
    }
}

__global__ void __launch_bounds__(THREADS, 7)
entmax15_kernel(const float* __restrict__ scores,
                const int*   __restrict__ mask,
                float*       __restrict__ out)
{
    const long long base = (long long)blockIdx.x * (ROWS_PER_CTA * S_LEN);
    const float4* s4 = reinterpret_cast<const float4*>(scores + base);
    const int4*   m4 = reinterpret_cast<const int4*>(mask + base);
    float4*       o4 = reinterpret_cast<float4*>(out + base);

    const int tid  = threadIdx.x;
    const int warp = tid >> 5;
    const int lane = tid & 31;

    __shared__ Smem sm;

    // ---- row0: load + extract ----
    float x[EPT];
    {
        float4 a[V4]; int4 m[V4];
        #pragma unroll
        for (int v = 0; v < V4; ++v) {
            a[v] = s4[tid + v * THREADS];
            m[v] = m4[tid + v * THREADS];
        }
        #pragma unroll
        for (int v = 0; v < V4; ++v) {
            x[v * 4 + 0] = m[v].x ? a[v].x : NEG_FILL;
            x[v * 4 + 1] = m[v].y ? a[v].y : NEG_FILL;
            x[v * 4 + 2] = m[v].z ? a[v].z : NEG_FILL;
            x[v * 4 + 3] = m[v].w ? a[v].w : NEG_FILL;
        }
    }

    // ---- issue row1 loads now; they fly during row0's max+solve ----
    float4 a1[V4]; int4 m1[V4];
    #pragma unroll
    for (int v = 0; v < V4; ++v) {
        a1[v] = s4[ROW4 + tid + v * THREADS];
        m1[v] = m4[ROW4 + tid + v * THREADS];
    }

    // ---- row0: max/transform, solve, store ----
    block_max_transform(x, sm.shmax[0], warp, lane);
    float tau = solve_tau(x, sm.red[0], warp, lane);
    emit(o4, x, tau, tid);

    // ---- row1: extract (loads have long landed), max, solve, store ----
    #pragma unroll
    for (int v = 0; v < V4; ++v) {
        x[v * 4 + 0] = m1[v].x ? a1[v].x : NEG_FILL;
        x[v * 4 + 1] = m1[v].y ? a1[v].y : NEG_FILL;
        x[v * 4 + 2] = m1[v].z ? a1[v].z : NEG_FILL;
        x[v * 4 + 3] = m1[v].w ? a1[v].w : NEG_FILL;
    }
    block_max_transform(x, sm.shmax[1], warp, lane);
    tau = solve_tau(x, sm.red[1], warp, lane);
    emit(o4 + ROW4, x, tau, tid);
}

extern "C" void kernel_launch(void* const* d_in, const int* in_sizes, int n_in,
                              void* d_out, int out_size)
{
    const float* scores = (const float*)d_in[0];
    const int*   mask   = (const int*)d_in[1];
    float*       out    = (float*)d_out;
    const int rows = in_sizes[0] / S_LEN;
    entmax15_kernel<<<rows / ROWS_PER_CTA, THREADS>>>(scores, mask, out);
}